// round 5
// baseline (speedup 1.0000x reference)
#include <cuda_runtime.h>
#include <cuda_bf16.h>
#include <cstddef>

// Problem shape (fixed per reference): feats [B, C, H, W] fp32, R [H, C, C] fp32.
#define Bn 16
#define Cn 256
#define Hn 128
#define Wn 128
#define Kn (Cn / 2)   // 128 channel pairs

// cos/sin table, indexed [h * Kn + k]. 128*128 float2 = 128 KB (L2-resident).
__device__ float2 g_cs[Hn * Kn];

// Extract the 2 nonzeros per RoPE 2x2 block from the dense rotation matrix:
//   cos = R[h, 2k,   2k]
//   sin = R[h, 2k+1, 2k]   (the +sin entry; c even column)
__global__ void rope_precompute_cs(const float* __restrict__ R) {
    int idx = blockIdx.x * blockDim.x + threadIdx.x;   // 0 .. Hn*Kn-1
    int h = idx >> 7;          // / Kn
    int k = idx & (Kn - 1);    // % Kn
    const float* Rh = R + (size_t)h * Cn * Cn;
    float c = Rh[(size_t)(2 * k) * Cn + 2 * k];
    float s = Rh[(size_t)(2 * k + 1) * Cn + 2 * k];
    g_cs[idx] = make_float2(c, s);
}

// Pure streaming rotation. One thread = one (b, k, h, w4) tile:
//   reads  float4 even = feats[b, 2k,   h, 4*w4 .. +3]
//          float4 odd  = feats[b, 2k+1, h, 4*w4 .. +3]
//   writes the rotated pair to the same locations in out.
// Low 5 bits = w4 so each warp streams one contiguous 128-float row
// (fully coalesced 128B transactions); cos/sin load is warp-uniform.
__global__ void __launch_bounds__(256) rope_rotate_kernel(
    const float* __restrict__ f, float* __restrict__ out) {
    unsigned tid = blockIdx.x * blockDim.x + threadIdx.x;
    unsigned w4 = tid & 31u;            // W/4 = 32
    unsigned h  = (tid >> 5) & 127u;    // Hn
    unsigned k  = (tid >> 12) & 127u;   // Kn
    unsigned b  = tid >> 19;            // Bn

    float2 cs = g_cs[(h << 7) | k];     // broadcast within warp

    size_t base = ((((size_t)b * Cn + 2u * k) * Hn + h) * Wn) + 4u * w4;
    const float4 e = *reinterpret_cast<const float4*>(f + base);
    const float4 o = *reinterpret_cast<const float4*>(f + base + (size_t)Hn * Wn);

    float4 re, ro;
    re.x = cs.x * e.x - cs.y * o.x;  ro.x = cs.y * e.x + cs.x * o.x;
    re.y = cs.x * e.y - cs.y * o.y;  ro.y = cs.y * e.y + cs.x * o.y;
    re.z = cs.x * e.z - cs.y * o.z;  ro.z = cs.y * e.z + cs.x * o.z;
    re.w = cs.x * e.w - cs.y * o.w;  ro.w = cs.y * e.w + cs.x * o.w;

    *reinterpret_cast<float4*>(out + base) = re;
    *reinterpret_cast<float4*>(out + base + (size_t)Hn * Wn) = ro;
}

extern "C" void kernel_launch(void* const* d_in, const int* in_sizes, int n_in,
                              void* d_out, int out_size) {
    const float* feats = (const float*)d_in[0];   // [16, 256, 128, 128]
    const float* rota  = (const float*)d_in[1];   // [128, 256, 256]
    float* out = (float*)d_out;                   // [16, 256, 128, 128]
    (void)in_sizes; (void)n_in; (void)out_size;

    // 1) Build the 128 KB cos/sin table from the dense R input.
    rope_precompute_cs<<<(Hn * Kn) / 256, 256>>>(rota);

    // 2) Stream-rotate: Bn*Kn*Hn*(Wn/4) = 16,777,216 threads.
    const unsigned total = Bn * Kn * Hn * (Wn / 4);
    rope_rotate_kernel<<<total / 256, 256>>>(feats, out);
}

// round 8
// speedup vs baseline: 1.0261x; 1.0261x over previous
#include <cuda_runtime.h>
#include <cuda_bf16.h>
#include <cstddef>

// Problem shape (fixed per reference): feats [B, C, H, W] fp32, R [H, C, C] fp32.
#define Bn 16
#define Cn 256
#define Hn 128
#define Wn 128
#define Kn (Cn / 2)   // 128 channel pairs

// Fused streaming rotation. One thread = one (b, k, h, w4) tile.
// Low 5 bits = w4, so within a warp (b, k, h) are fixed:
//   -> cos/sin loads from R are warp-uniform (1 sector, broadcast),
//      L2-cached across the 16 batches that share each (h, k).
//   reads  float4 even = feats[b, 2k,   h, 4*w4 .. +3]
//          float4 odd  = feats[b, 2k+1, h, 4*w4 .. +3]
//   writes the rotated pair to the same locations in out.
// feats/out have zero reuse -> streaming hints (__ldcs/__stcs) keep them
// from evicting the R-diagonal lines in L2.
__global__ void __launch_bounds__(256) rope_rotate_fused_kernel(
    const float* __restrict__ f,
    const float* __restrict__ R,
    float* __restrict__ out) {
    unsigned tid = blockIdx.x * blockDim.x + threadIdx.x;
    unsigned w4 = tid & 31u;            // W/4 = 32
    unsigned h  = (tid >> 5) & 127u;    // Hn
    unsigned k  = (tid >> 12) & 127u;   // Kn
    unsigned b  = tid >> 19;            // Bn

    // Warp-uniform 2x2 block extraction from the dense rotation matrix:
    //   cos = R[h, 2k,   2k]
    //   sin = R[h, 2k+1, 2k]   (the +sin entry; c even column)
    const float* Rh = R + (size_t)h * (Cn * Cn) + (size_t)(2u * k) * Cn + 2u * k;
    float cosv = __ldg(Rh);
    float sinv = __ldg(Rh + Cn);

    size_t base = ((((size_t)b * Cn + 2u * k) * Hn + h) * Wn) + 4u * w4;
    const float4 e = __ldcs(reinterpret_cast<const float4*>(f + base));
    const float4 o = __ldcs(reinterpret_cast<const float4*>(f + base + (size_t)Hn * Wn));

    float4 re, ro;
    re.x = cosv * e.x - sinv * o.x;  ro.x = sinv * e.x + cosv * o.x;
    re.y = cosv * e.y - sinv * o.y;  ro.y = sinv * e.y + cosv * o.y;
    re.z = cosv * e.z - sinv * o.z;  ro.z = sinv * e.z + cosv * o.z;
    re.w = cosv * e.w - sinv * o.w;  ro.w = sinv * e.w + cosv * o.w;

    __stcs(reinterpret_cast<float4*>(out + base), re);
    __stcs(reinterpret_cast<float4*>(out + base + (size_t)Hn * Wn), ro);
}

extern "C" void kernel_launch(void* const* d_in, const int* in_sizes, int n_in,
                              void* d_out, int out_size) {
    const float* feats = (const float*)d_in[0];   // [16, 256, 128, 128]
    const float* rota  = (const float*)d_in[1];   // [128, 256, 256]
    float* out = (float*)d_out;                   // [16, 256, 128, 128]
    (void)in_sizes; (void)n_in; (void)out_size;

    // Single fused launch: Bn*Kn*Hn*(Wn/4) = 16,777,216 threads.
    const unsigned total = Bn * Kn * Hn * (Wn / 4);
    rope_rotate_fused_kernel<<<total / 256, 256>>>(feats, rota, out);
}